// round 13
// baseline (speedup 1.0000x reference)
#include <cuda_runtime.h>
#include <cuda_bf16.h>
#include <cstdint>

// LinearSelfAttention, factored:
//   G  = H[:, :2048] @ H[:, :2048]^T   (mask == K-truncation; G symmetric)
//   T1 = P @ G ;  A2 = T1 @ Q ;  out = H + (A2 @ H) / 2048
// bf16 mma.sync + ldmatrix, SW128 smem, 128x128 tiles, 3-stage cp.async.
// G: split-K=2 ([G0|G1], combine folded into step 2 as T1=[P|P]@[G0|G1]^T)
//    AND triangular (only 6/9 tiles computed; off-diag mirrored bit-exact).

#define BATCH 16
#define D_REAL 257
#define N_REAL 2049
#define HSTR   (257L * 2049L)

#define DP 384      // padded d as M/N (mult of 128)
#define DK 320      // padded d as K   (mult of 64)
#define NP 2176     // padded n        (mult of 128)
#define NSTG 3
#define BK 64       // K per chunk = 128 B per row = SW128 atom
#define GLD 768     // row stride of [G0|G1] and [P|P]

__device__ __align__(256) __nv_bfloat16 g_Hb [BATCH * DP * NP];
__device__ __align__(256) __nv_bfloat16 g_HbT[BATCH * NP * DP];
__device__ __align__(256) __nv_bfloat16 g_Pb2[DP * GLD];          // [P|P]
__device__ __align__(256) __nv_bfloat16 g_QbT[DP * DK];
__device__ __align__(256) __nv_bfloat16 g_Gp [BATCH * DP * GLD];  // [G0|G1]
__device__ __align__(256) __nv_bfloat16 g_S1 [BATCH * DP * DP];
__device__ __align__(256) __nv_bfloat16 g_S2 [BATCH * DP * DP];

// ---------------------------------------------------------------- helpers

__device__ __forceinline__ uint32_t smem_u32(const void* p) {
    uint32_t a;
    asm("{ .reg .u64 t; cvta.to.shared.u64 t, %1; cvt.u32.u64 %0, t; }"
        : "=r"(a) : "l"(p));
    return a;
}

__device__ __forceinline__ void cp16s(uint32_t dst, const void* src) {
    asm volatile("cp.async.cg.shared.global [%0], [%1], 16;\n" :: "r"(dst), "l"(src));
}

#define SWZ(off) ((off) ^ (((off) >> 3) & 0x70))

__device__ __forceinline__ void ldm_x4(uint32_t* r, uint32_t addr) {
    asm volatile("ldmatrix.sync.aligned.m8n8.x4.shared.b16 {%0,%1,%2,%3}, [%4];"
                 : "=r"(r[0]), "=r"(r[1]), "=r"(r[2]), "=r"(r[3]) : "r"(addr));
}

__device__ __forceinline__ void mma16816(float* d, const uint32_t* a,
                                         uint32_t b0, uint32_t b1) {
    asm volatile(
        "mma.sync.aligned.m16n8k16.row.col.f32.bf16.bf16.f32 "
        "{%0,%1,%2,%3}, {%4,%5,%6,%7}, {%8,%9}, {%0,%1,%2,%3};"
        : "+f"(d[0]), "+f"(d[1]), "+f"(d[2]), "+f"(d[3])
        : "r"(a[0]), "r"(a[1]), "r"(a[2]), "r"(a[3]), "r"(b0), "r"(b1));
}

// ---------------------------------------------------------------- converts

__global__ void conv_H(const float* __restrict__ H,
                       __nv_bfloat16* __restrict__ Hb,
                       __nv_bfloat16* __restrict__ HbT)
{
    __shared__ float t[32][33];
    const int b  = blockIdx.z;
    const int n0 = blockIdx.x * 32;
    const int d0 = blockIdx.y * 32;
    const int tid = threadIdx.x;           // 256
    const int tx = tid & 31, ty = tid >> 5;
    const float* Hp = H + (long)b * HSTR;

    #pragma unroll
    for (int i = 0; i < 4; i++) {
        int d = d0 + ty + i * 8, n = n0 + tx;
        float v = 0.f;
        if (d < D_REAL && n < N_REAL) v = Hp[(long)d * N_REAL + n];
        t[ty + i * 8][tx] = v;
    }
    __syncthreads();

    // store phase: 8-byte vectorized (4 x bf16 per thread per dest)
    const int c4 = (tid & 7) * 4;   // col group of 4
    const int r  = tid >> 3;        // 0..31
    __nv_bfloat16* Hbp  = Hb  + (long)b * DP * NP;
    __nv_bfloat16* HbTp = HbT + (long)b * NP * DP;

    {   // Hb[d0+r][n0+c4 .. +3] = t[r][c4..c4+3]
        __nv_bfloat162 p0, p1;
        p0.x = __float2bfloat16(t[r][c4 + 0]);
        p0.y = __float2bfloat16(t[r][c4 + 1]);
        p1.x = __float2bfloat16(t[r][c4 + 2]);
        p1.y = __float2bfloat16(t[r][c4 + 3]);
        uint2 u;
        u.x = *(uint32_t*)&p0;
        u.y = *(uint32_t*)&p1;
        *(uint2*)&Hbp[(long)(d0 + r) * NP + n0 + c4] = u;
    }
    {   // HbT[n0+r][d0+c4 .. +3] = t[c4..c4+3][r]   (conflict-free: 4tx+ty unique/warp)
        __nv_bfloat162 p0, p1;
        p0.x = __float2bfloat16(t[c4 + 0][r]);
        p0.y = __float2bfloat16(t[c4 + 1][r]);
        p1.x = __float2bfloat16(t[c4 + 2][r]);
        p1.y = __float2bfloat16(t[c4 + 3][r]);
        uint2 u;
        u.x = *(uint32_t*)&p0;
        u.y = *(uint32_t*)&p1;
        *(uint2*)&HbTp[(long)(n0 + r) * DP + d0 + c4] = u;
    }
}

__global__ void conv_P2(const float* __restrict__ P, __nv_bfloat16* __restrict__ Pb2)
{
    int idx = blockIdx.x * blockDim.x + threadIdx.x;
    if (idx >= DP * GLD) return;
    int r = idx / GLD, c = idx % GLD;
    int k = (c >= DP) ? c - DP : c;
    Pb2[idx] = __float2bfloat16((r < D_REAL && k < D_REAL) ? P[r * D_REAL + k] : 0.f);
}

__global__ void conv_QT(const float* __restrict__ Q, __nv_bfloat16* __restrict__ QbT)
{
    int idx = blockIdx.x * blockDim.x + threadIdx.x;
    if (idx >= DP * DK) return;
    int n = idx / DK, k = idx % DK;
    QbT[idx] = __float2bfloat16((n < D_REAL && k < D_REAL) ? Q[k * D_REAL + n] : 0.f);
}

// Mirror upper tiles of each G half from the computed lower tiles (bit-exact).
// grid (4, 4, BATCH*6): z -> (batch, half, t in {(1,0),(2,0),(2,1)})
__global__ void mirror_G(__nv_bfloat16* __restrict__ Gp)
{
    __shared__ __nv_bfloat16 s[32][33];
    const int z = blockIdx.z;
    const int batch = z / 6;
    const int rem = z % 6;
    const int half = rem / 3;
    const int t = rem % 3;
    const int SM_[3] = {1, 2, 2};
    const int SN_[3] = {0, 0, 1};

    __nv_bfloat16* Gb = Gp + (long)batch * DP * GLD;
    const int R0 = SM_[t] * 128 + blockIdx.y * 32;              // src rows
    const int C0 = SN_[t] * 128 + blockIdx.x * 32;              // src cols (in-half)
    const int R1 = SN_[t] * 128 + blockIdx.x * 32;              // dst rows
    const int C1 = SM_[t] * 128 + blockIdx.y * 32;              // dst cols (in-half)
    const int co = half * DP;

    const int tid = threadIdx.x;
    const int tx = tid & 31, ty = tid >> 5;
    #pragma unroll
    for (int i = 0; i < 4; i++)
        s[ty + i * 8][tx] = Gb[(long)(R0 + ty + i * 8) * GLD + co + C0 + tx];
    __syncthreads();
    #pragma unroll
    for (int i = 0; i < 4; i++)
        Gb[(long)(R1 + ty + i * 8) * GLD + co + C1 + tx] = s[tx][ty + i * 8];
}

// ---------------------------------------------------------------- GEMM NT

// C[M,N] = scale * A[M,K] @ B[N,K]^T. 128x128 CTA tile, warp tile 64x32.
// MODE=0: plain (bm = blockIdx.y*128).
// MODE=1: split-K=2 (blockIdx.y = mtile*2+split), C cols shift split*DP.
// MODE=2: triangular split-K=2: blockIdx.y = p*2+split, p -> lower-tri (mi,ni).
// EPI=0: bf16 to Cb (padded). EPI=1: fp32 out = Hadd + acc*scale, guarded.
template<int EPI, int MODE>
__global__ void __launch_bounds__(256, 2)
gemm_nt(const __nv_bfloat16* __restrict__ A,
        const __nv_bfloat16* __restrict__ B,
        __nv_bfloat16* __restrict__ Cb,
        float* __restrict__ Cf,
        const float* __restrict__ Hadd,
        int K, int lda, int ldb, int ldc,
        long sA, long sB, long sC, float scale)
{
    extern __shared__ __align__(1024) char dyn[];
    const int bz = blockIdx.z;
    A += (long)bz * sA;
    B += (long)bz * sB;

    int bm, bn, cshift;
    if (MODE == 2) {
        const int p = blockIdx.y >> 1;
        const int split = blockIdx.y & 1;
        int mi, ni;
        if      (p == 0) { mi = 0; ni = 0; }
        else if (p == 1) { mi = 1; ni = 0; }
        else if (p == 2) { mi = 1; ni = 1; }
        else if (p == 3) { mi = 2; ni = 0; }
        else if (p == 4) { mi = 2; ni = 1; }
        else             { mi = 2; ni = 2; }
        bm = mi * 128; bn = ni * 128;
        cshift = split * DP;
        A += split * 1024;
        B += split * 1024;
    } else if (MODE == 1) {
        const int split = blockIdx.y & 1;
        bm = (blockIdx.y >> 1) * 128;
        bn = blockIdx.x * 128;
        cshift = split * DP;
        A += split * 1024;
        B += split * 1024;
    } else {
        bm = blockIdx.y * 128;
        bn = blockIdx.x * 128;
        cshift = 0;
    }
    const int tid  = threadIdx.x;
    const int lane = tid & 31;
    const int wid  = tid >> 5;
    const int g    = lane >> 2;
    const int tig  = lane & 3;
    const int wm   = (wid & 1) * 64;     // 2 warps over m
    const int wn   = (wid >> 1) * 32;    // 4 warps over n

    const uint32_t base = smem_u32(dyn);  // [NSTG][A:16KB | B:16KB]

    float acc[4][4][4];
    #pragma unroll
    for (int i = 0; i < 4; i++)
        #pragma unroll
        for (int j = 0; j < 4; j++)
            #pragma unroll
            for (int r = 0; r < 4; r++) acc[i][j][r] = 0.f;

    const uint32_t swx      = (uint32_t)((lane & 7) << 4);
    const uint32_t a_rowoff = (uint32_t)(wm + (lane & 15)) * 128;
    const uint32_t a_koff   = (uint32_t)((lane >> 4) * 16);
    const uint32_t b_rowoff = (uint32_t)(wn + (lane & 7) + ((lane >> 4) & 1) * 8) * 128;
    const uint32_t b_koff   = (uint32_t)(((lane >> 3) & 1) * 16);

    auto load_chunk = [&](int c) {
        const int st = c % NSTG;
        const uint32_t ab = base + st * 32768;
        const uint32_t bb = ab + 16384;
        const int k0 = c * BK;
        #pragma unroll
        for (int i = 0; i < 4; i++) {
            int ch  = tid + i * 256;
            int row = ch >> 3;
            int q   = ch & 7;
            uint32_t off = SWZ(row * 128 + q * 16);
            cp16s(ab + off, A + (long)(bm + row) * lda + k0 + q * 8);
            cp16s(bb + off, B + (long)(bn + row) * ldb + k0 + q * 8);
        }
        asm volatile("cp.async.commit_group;");
    };

    const int nk = K / BK;   // >= NSTG at every call site
    load_chunk(0);
    load_chunk(1);

    for (int kt = 0; kt < nk; kt++) {
        if (kt + 2 < nk) load_chunk(kt + 2);
        else asm volatile("cp.async.commit_group;");
        asm volatile("cp.async.wait_group %0;" :: "n"(NSTG - 1));
        __syncthreads();

        const uint32_t ab = base + (kt % NSTG) * 32768;
        const uint32_t bb = ab + 16384;

        #pragma unroll
        for (int kk = 0; kk < 4; kk++) {               // 4 x k16 per BK=64
            uint32_t af[4][4], bf[2][4];
            #pragma unroll
            for (int mi = 0; mi < 4; mi++)
                ldm_x4(af[mi], ab + a_rowoff + mi * 2048
                               + ((uint32_t)(kk * 32) + a_koff ^ swx));
            #pragma unroll
            for (int p = 0; p < 2; p++)
                ldm_x4(bf[p], bb + b_rowoff + p * 2048
                              + ((uint32_t)(kk * 32) + b_koff ^ swx));
            #pragma unroll
            for (int mi = 0; mi < 4; mi++)
                #pragma unroll
                for (int ni = 0; ni < 4; ni++)
                    mma16816(acc[mi][ni], af[mi],
                             bf[ni >> 1][(ni & 1) * 2], bf[ni >> 1][(ni & 1) * 2 + 1]);
        }
        __syncthreads();
    }

    if (EPI == 0) {
        __nv_bfloat16* Cp = Cb + (long)bz * sC;
        #pragma unroll
        for (int mi = 0; mi < 4; mi++) {
            int r0 = bm + wm + mi * 16 + g;
            #pragma unroll
            for (int ni = 0; ni < 4; ni++) {
                int c = cshift + bn + wn + ni * 8 + tig * 2;
                __nv_bfloat162 v01, v23;
                v01.x = __float2bfloat16(acc[mi][ni][0] * scale);
                v01.y = __float2bfloat16(acc[mi][ni][1] * scale);
                v23.x = __float2bfloat16(acc[mi][ni][2] * scale);
                v23.y = __float2bfloat16(acc[mi][ni][3] * scale);
                *(__nv_bfloat162*)&Cp[(long)r0 * ldc + c]       = v01;
                *(__nv_bfloat162*)&Cp[(long)(r0 + 8) * ldc + c] = v23;
            }
        }
    } else {
        const float* Hp = Hadd + (long)bz * HSTR;
        float*       Op = Cf   + (long)bz * HSTR;
        #pragma unroll
        for (int mi = 0; mi < 4; mi++) {
            int r0 = bm + wm + mi * 16 + g;
            #pragma unroll
            for (int ni = 0; ni < 4; ni++) {
                int c = bn + wn + ni * 8 + tig * 2;
                #pragma unroll
                for (int half = 0; half < 2; half++) {
                    int r = r0 + half * 8;
                    if (r < D_REAL) {
                        if (c < N_REAL) {
                            long idx = (long)r * N_REAL + c;
                            Op[idx] = Hp[idx] + acc[mi][ni][half * 2 + 0] * scale;
                        }
                        if (c + 1 < N_REAL) {
                            long idx = (long)r * N_REAL + c + 1;
                            Op[idx] = Hp[idx] + acc[mi][ni][half * 2 + 1] * scale;
                        }
                    }
                }
            }
        }
    }
}

// ---------------------------------------------------------------- launch

extern "C" void kernel_launch(void* const* d_in, const int* in_sizes, int n_in,
                              void* d_out, int out_size)
{
    const float* H = (const float*)d_in[0];
    const float* P = (const float*)d_in[1];
    const float* Q = (const float*)d_in[2];
    float* out = (float*)d_out;

    void *pHb, *pHbT, *pPb2, *pQbT, *pGp, *pS1, *pS2;
    cudaGetSymbolAddress(&pHb,  g_Hb);
    cudaGetSymbolAddress(&pHbT, g_HbT);
    cudaGetSymbolAddress(&pPb2, g_Pb2);
    cudaGetSymbolAddress(&pQbT, g_QbT);
    cudaGetSymbolAddress(&pGp,  g_Gp);
    cudaGetSymbolAddress(&pS1,  g_S1);
    cudaGetSymbolAddress(&pS2,  g_S2);
    __nv_bfloat16* Hb  = (__nv_bfloat16*)pHb;
    __nv_bfloat16* HbT = (__nv_bfloat16*)pHbT;
    __nv_bfloat16* Pb2 = (__nv_bfloat16*)pPb2;
    __nv_bfloat16* QbT = (__nv_bfloat16*)pQbT;
    __nv_bfloat16* Gp  = (__nv_bfloat16*)pGp;
    __nv_bfloat16* S1  = (__nv_bfloat16*)pS1;
    __nv_bfloat16* S2  = (__nv_bfloat16*)pS2;

    const long sHN = (long)DP * NP;
    const long sNT = (long)NP * DP;
    const long sDD = (long)DP * DP;
    const long sG  = (long)DP * GLD;

    conv_H <<<dim3(NP / 32, DP / 32, BATCH), 256>>>(H, Hb, HbT);
    conv_P2<<<(DP * GLD + 255) / 256, 256>>>(P, Pb2);
    conv_QT<<<(DP * DK + 255) / 256, 256>>>(Q, QbT);

    const int smem = NSTG * 32768;   // 96 KB
    cudaFuncSetAttribute(gemm_nt<0, 0>, cudaFuncAttributeMaxDynamicSharedMemorySize, smem);
    cudaFuncSetAttribute(gemm_nt<0, 2>, cudaFuncAttributeMaxDynamicSharedMemorySize, smem);
    cudaFuncSetAttribute(gemm_nt<1, 0>, cudaFuncAttributeMaxDynamicSharedMemorySize, smem);

    dim3 blk(256);
    dim3 gG   (1, 12, BATCH);                     // 6 lower-tri tiles x 2 splits
    dim3 gSq  (DP / 128, DP / 128, BATCH);        // 3 x 3 x 16 = 144
    dim3 gWide(NP / 128, DP / 128, BATCH);        // 17 x 3 x 16 = 816

    // 1) lower-tri of [G0|G1] = H @ H^T over K halves 1024+1024
    gemm_nt<0, 2><<<gG, blk, smem>>>(Hb, Hb, Gp, nullptr, nullptr,
                                     1024, NP, NP, GLD, sHN, sHN, sG, 1.f);
    // 1b) mirror upper tiles (bit-exact transpose of lower tiles)
    mirror_G<<<dim3(4, 4, BATCH * 6), 256>>>(Gp);
    // 2) T1 = [P|P] @ [G0|G1]^T  (K=768 performs the split-K combine)
    gemm_nt<0, 0><<<gSq, blk, smem>>>(Pb2, Gp, S2, nullptr, nullptr,
                                      GLD, GLD, GLD, DP, 0, sG, sDD, 1.f);
    // 3) A2 = T1 @ Q
    gemm_nt<0, 0><<<gSq, blk, smem>>>(S2, QbT, S1, nullptr, nullptr,
                                      DK, DP, DK, DP, sDD, 0, sDD, 1.f);
    // 4) out = H + (A2 @ H) / 2048
    gemm_nt<1, 0><<<gWide, blk, smem>>>(S1, HbT, nullptr, out, H,
                                        DK, DP, DP, 0, sDD, sNT, 0, 1.f / 2048.f);
}

// round 15
// speedup vs baseline: 1.0462x; 1.0462x over previous
#include <cuda_runtime.h>
#include <cuda_bf16.h>
#include <cstdint>

// LinearSelfAttention, factored:
//   G  = H[:, :2048] @ H[:, :2048]^T   (mask == K-truncation; G symmetric)
//   T1 = P @ G ;  A2 = T1 @ Q ;  out = H + (A2 @ H) / 2048
// bf16 mma.sync + ldmatrix, SW128 smem, 3-stage cp.async.
// MI=4: 128x128 CTA tile (G). MI=2: 64x128 tile (small GEMMs + epilogue GEMM).
// EPI=1 stages acc through smem and streams H/out with full-sector coalescing.

#define BATCH 16
#define D_REAL 257
#define N_REAL 2049
#define HSTR   (257L * 2049L)

#define DP 384      // padded d as M/N (mult of 128)
#define DK 320      // padded d as K   (mult of 64)
#define NP 2176     // padded n        (mult of 128)
#define NSTG 3
#define BK 64       // K per chunk = 128 B per row = SW128 atom

__device__ __align__(256) __nv_bfloat16 g_Hb [BATCH * DP * NP];
__device__ __align__(256) __nv_bfloat16 g_HbT[BATCH * NP * DP];
__device__ __align__(256) __nv_bfloat16 g_Pb [DP * DK];
__device__ __align__(256) __nv_bfloat16 g_QbT[DP * DK];
__device__ __align__(256) __nv_bfloat16 g_S1 [BATCH * DP * DP];
__device__ __align__(256) __nv_bfloat16 g_S2 [BATCH * DP * DP];

// ---------------------------------------------------------------- helpers

__device__ __forceinline__ uint32_t smem_u32(const void* p) {
    uint32_t a;
    asm("{ .reg .u64 t; cvta.to.shared.u64 t, %1; cvt.u32.u64 %0, t; }"
        : "=r"(a) : "l"(p));
    return a;
}

__device__ __forceinline__ void cp16s(uint32_t dst, const void* src) {
    asm volatile("cp.async.cg.shared.global [%0], [%1], 16;\n" :: "r"(dst), "l"(src));
}

#define SWZ(off) ((off) ^ (((off) >> 3) & 0x70))

__device__ __forceinline__ void ldm_x4(uint32_t* r, uint32_t addr) {
    asm volatile("ldmatrix.sync.aligned.m8n8.x4.shared.b16 {%0,%1,%2,%3}, [%4];"
                 : "=r"(r[0]), "=r"(r[1]), "=r"(r[2]), "=r"(r[3]) : "r"(addr));
}

__device__ __forceinline__ void mma16816(float* d, const uint32_t* a,
                                         uint32_t b0, uint32_t b1) {
    asm volatile(
        "mma.sync.aligned.m16n8k16.row.col.f32.bf16.bf16.f32 "
        "{%0,%1,%2,%3}, {%4,%5,%6,%7}, {%8,%9}, {%0,%1,%2,%3};"
        : "+f"(d[0]), "+f"(d[1]), "+f"(d[2]), "+f"(d[3])
        : "r"(a[0]), "r"(a[1]), "r"(a[2]), "r"(a[3]), "r"(b0), "r"(b1));
}

// ---------------------------------------------------------------- converts

__global__ void conv_H(const float* __restrict__ H,
                       __nv_bfloat16* __restrict__ Hb,
                       __nv_bfloat16* __restrict__ HbT)
{
    __shared__ float t[32][33];
    const int b  = blockIdx.z;
    const int n0 = blockIdx.x * 32;
    const int d0 = blockIdx.y * 32;
    const int tid = threadIdx.x;           // 256
    const int tx = tid & 31, ty = tid >> 5;
    const float* Hp = H + (long)b * HSTR;

    #pragma unroll
    for (int i = 0; i < 4; i++) {
        int d = d0 + ty + i * 8, n = n0 + tx;
        float v = 0.f;
        if (d < D_REAL && n < N_REAL) v = Hp[(long)d * N_REAL + n];
        t[ty + i * 8][tx] = v;
    }
    __syncthreads();

    const int c4 = (tid & 7) * 4;
    const int r  = tid >> 3;
    __nv_bfloat16* Hbp  = Hb  + (long)b * DP * NP;
    __nv_bfloat16* HbTp = HbT + (long)b * NP * DP;

    {
        __nv_bfloat162 p0, p1;
        p0.x = __float2bfloat16(t[r][c4 + 0]);
        p0.y = __float2bfloat16(t[r][c4 + 1]);
        p1.x = __float2bfloat16(t[r][c4 + 2]);
        p1.y = __float2bfloat16(t[r][c4 + 3]);
        uint2 u;
        u.x = *(uint32_t*)&p0;
        u.y = *(uint32_t*)&p1;
        *(uint2*)&Hbp[(long)(d0 + r) * NP + n0 + c4] = u;
    }
    {
        __nv_bfloat162 p0, p1;
        p0.x = __float2bfloat16(t[c4 + 0][r]);
        p0.y = __float2bfloat16(t[c4 + 1][r]);
        p1.x = __float2bfloat16(t[c4 + 2][r]);
        p1.y = __float2bfloat16(t[c4 + 3][r]);
        uint2 u;
        u.x = *(uint32_t*)&p0;
        u.y = *(uint32_t*)&p1;
        *(uint2*)&HbTp[(long)(n0 + r) * DP + d0 + c4] = u;
    }
}

__global__ void conv_P(const float* __restrict__ P, __nv_bfloat16* __restrict__ Pb)
{
    int idx = blockIdx.x * blockDim.x + threadIdx.x;
    if (idx >= DP * DK) return;
    int r = idx / DK, c = idx % DK;
    Pb[idx] = __float2bfloat16((r < D_REAL && c < D_REAL) ? P[r * D_REAL + c] : 0.f);
}

__global__ void conv_QT(const float* __restrict__ Q, __nv_bfloat16* __restrict__ QbT)
{
    int idx = blockIdx.x * blockDim.x + threadIdx.x;
    if (idx >= DP * DK) return;
    int n = idx / DK, k = idx % DK;
    QbT[idx] = __float2bfloat16((n < D_REAL && k < D_REAL) ? Q[k * D_REAL + n] : 0.f);
}

// ---------------------------------------------------------------- GEMM NT

// C[M,N] = scale * A[M,K] @ B[N,K]^T. CTA tile (MI*32) x 128, warp tile (MI*16) x 32.
// EPI=0: bf16 to Cb (padded, unguarded).
// EPI=1: stage acc in smem, then out = Hadd + acc*scale with full-sector
//        coalesced streaming (128 consecutive 4B lanes per row), guarded.
template<int EPI, int MI>
__global__ void __launch_bounds__(256, 2)
gemm_nt(const __nv_bfloat16* __restrict__ A,
        const __nv_bfloat16* __restrict__ B,
        __nv_bfloat16* __restrict__ Cb,
        float* __restrict__ Cf,
        const float* __restrict__ Hadd,
        int K, int lda, int ldb, int ldc,
        long sA, long sB, long sC, float scale)
{
    constexpr int BM   = MI * 32;
    constexpr int ASZ  = BM * 128;        // A stage bytes
    constexpr int SSTR = ASZ + 16384;     // stage stride (A + B)

    extern __shared__ __align__(1024) char dyn[];
    const int bz = blockIdx.z;
    A += (long)bz * sA;
    B += (long)bz * sB;

    const int bm = blockIdx.y * BM;
    const int bn = blockIdx.x * 128;
    const int tid  = threadIdx.x;
    const int lane = tid & 31;
    const int wid  = tid >> 5;
    const int g    = lane >> 2;
    const int tig  = lane & 3;
    const int wm   = (wid & 1) * (MI * 16);   // 2 warps over m
    const int wn   = (wid >> 1) * 32;         // 4 warps over n

    const uint32_t base = smem_u32(dyn);

    float acc[MI][4][4];
    #pragma unroll
    for (int i = 0; i < MI; i++)
        #pragma unroll
        for (int j = 0; j < 4; j++)
            #pragma unroll
            for (int r = 0; r < 4; r++) acc[i][j][r] = 0.f;

    const uint32_t swx      = (uint32_t)((lane & 7) << 4);
    const uint32_t a_rowoff = (uint32_t)(wm + (lane & 15)) * 128;
    const uint32_t a_koff   = (uint32_t)((lane >> 4) * 16);
    const uint32_t b_rowoff = (uint32_t)(wn + (lane & 7) + ((lane >> 4) & 1) * 8) * 128;
    const uint32_t b_koff   = (uint32_t)(((lane >> 3) & 1) * 16);

    auto load_chunk = [&](int c) {
        const int st = c % NSTG;
        const uint32_t ab = base + st * SSTR;
        const uint32_t bb = ab + ASZ;
        const int k0 = c * BK;
        #pragma unroll
        for (int i = 0; i < MI; i++) {        // A: BM*8 16B-chunks
            int ch  = tid + i * 256;
            int row = ch >> 3;
            int q   = ch & 7;
            cp16s(ab + SWZ(row * 128 + q * 16),
                  A + (long)(bm + row) * lda + k0 + q * 8);
        }
        #pragma unroll
        for (int i = 0; i < 4; i++) {         // B: 1024 chunks
            int ch  = tid + i * 256;
            int row = ch >> 3;
            int q   = ch & 7;
            cp16s(bb + SWZ(row * 128 + q * 16),
                  B + (long)(bn + row) * ldb + k0 + q * 8);
        }
        asm volatile("cp.async.commit_group;");
    };

    const int nk = K / BK;   // >= NSTG at every call site
    load_chunk(0);
    load_chunk(1);

    for (int kt = 0; kt < nk; kt++) {
        if (kt + 2 < nk) load_chunk(kt + 2);
        else asm volatile("cp.async.commit_group;");
        asm volatile("cp.async.wait_group %0;" :: "n"(NSTG - 1));
        __syncthreads();

        const uint32_t ab = base + (kt % NSTG) * SSTR;
        const uint32_t bb = ab + ASZ;

        #pragma unroll
        for (int kk = 0; kk < 4; kk++) {               // 4 x k16 per BK=64
            uint32_t af[MI][4], bf[2][4];
            #pragma unroll
            for (int mi = 0; mi < MI; mi++)
                ldm_x4(af[mi], ab + a_rowoff + mi * 2048
                               + ((uint32_t)(kk * 32) + a_koff ^ swx));
            #pragma unroll
            for (int p = 0; p < 2; p++)
                ldm_x4(bf[p], bb + b_rowoff + p * 2048
                              + ((uint32_t)(kk * 32) + b_koff ^ swx));
            #pragma unroll
            for (int mi = 0; mi < MI; mi++)
                #pragma unroll
                for (int ni = 0; ni < 4; ni++)
                    mma16816(acc[mi][ni], af[mi],
                             bf[ni >> 1][(ni & 1) * 2], bf[ni >> 1][(ni & 1) * 2 + 1]);
        }
        __syncthreads();
    }

    if (EPI == 0) {
        __nv_bfloat16* Cp = Cb + (long)bz * sC;
        #pragma unroll
        for (int mi = 0; mi < MI; mi++) {
            int r0 = bm + wm + mi * 16 + g;
            #pragma unroll
            for (int ni = 0; ni < 4; ni++) {
                int c = bn + wn + ni * 8 + tig * 2;
                __nv_bfloat162 v01, v23;
                v01.x = __float2bfloat16(acc[mi][ni][0] * scale);
                v01.y = __float2bfloat16(acc[mi][ni][1] * scale);
                v23.x = __float2bfloat16(acc[mi][ni][2] * scale);
                v23.y = __float2bfloat16(acc[mi][ni][3] * scale);
                *(__nv_bfloat162*)&Cp[(long)r0 * ldc + c]       = v01;
                *(__nv_bfloat162*)&Cp[(long)(r0 + 8) * ldc + c] = v23;
            }
        }
    } else {
        // stage acc tile (BM x 128 fp32) in smem, then stream coalesced
        float* cs = (float*)dyn;
        #pragma unroll
        for (int mi = 0; mi < MI; mi++)
            #pragma unroll
            for (int ni = 0; ni < 4; ni++)
                #pragma unroll
                for (int half = 0; half < 2; half++) {
                    int row = wm + mi * 16 + g + half * 8;
                    int col = wn + ni * 8 + tig * 2;
                    float2 v;
                    v.x = acc[mi][ni][half * 2 + 0] * scale;
                    v.y = acc[mi][ni][half * 2 + 1] * scale;
                    *(float2*)&cs[row * 128 + col] = v;
                }
        __syncthreads();

        const float* Hp = Hadd + (long)bz * HSTR;
        float*       Op = Cf   + (long)bz * HSTR;
        const int lcol = tid & 127;          // 0..127
        const int gcol = bn + lcol;
        if (gcol < N_REAL) {
            #pragma unroll 4
            for (int rr = tid >> 7; rr < BM; rr += 2) {
                int grow = bm + rr;
                if (grow < D_REAL) {
                    long idx = (long)grow * N_REAL + gcol;
                    Op[idx] = Hp[idx] + cs[rr * 128 + lcol];
                }
            }
        }
    }
}

// ---------------------------------------------------------------- launch

extern "C" void kernel_launch(void* const* d_in, const int* in_sizes, int n_in,
                              void* d_out, int out_size)
{
    const float* H = (const float*)d_in[0];
    const float* P = (const float*)d_in[1];
    const float* Q = (const float*)d_in[2];
    float* out = (float*)d_out;

    void *pHb, *pHbT, *pPb, *pQbT, *pS1, *pS2;
    cudaGetSymbolAddress(&pHb,  g_Hb);
    cudaGetSymbolAddress(&pHbT, g_HbT);
    cudaGetSymbolAddress(&pPb,  g_Pb);
    cudaGetSymbolAddress(&pQbT, g_QbT);
    cudaGetSymbolAddress(&pS1,  g_S1);
    cudaGetSymbolAddress(&pS2,  g_S2);
    __nv_bfloat16* Hb  = (__nv_bfloat16*)pHb;
    __nv_bfloat16* HbT = (__nv_bfloat16*)pHbT;
    __nv_bfloat16* Pb  = (__nv_bfloat16*)pPb;
    __nv_bfloat16* QbT = (__nv_bfloat16*)pQbT;
    __nv_bfloat16* S1  = (__nv_bfloat16*)pS1;
    __nv_bfloat16* S2  = (__nv_bfloat16*)pS2;

    const long sHN = (long)DP * NP;
    const long sNT = (long)NP * DP;
    const long sDD = (long)DP * DP;

    conv_H <<<dim3(NP / 32, DP / 32, BATCH), 256>>>(H, Hb, HbT);
    conv_P <<<(DP * DK + 255) / 256, 256>>>(P, Pb);
    conv_QT<<<(DP * DK + 255) / 256, 256>>>(Q, QbT);

    const int smem4 = NSTG * (128 * 128 + 16384);   // 96 KB (MI=4)
    const int smem2 = NSTG * (64 * 128 + 16384);    // 72 KB (MI=2)
    cudaFuncSetAttribute(gemm_nt<0, 4>, cudaFuncAttributeMaxDynamicSharedMemorySize, smem4);
    cudaFuncSetAttribute(gemm_nt<0, 2>, cudaFuncAttributeMaxDynamicSharedMemorySize, smem2);
    cudaFuncSetAttribute(gemm_nt<1, 2>, cudaFuncAttributeMaxDynamicSharedMemorySize, smem2);

    dim3 blk(256);
    dim3 gG   (DP / 128, DP / 128, BATCH);   // 3 x 3 x 16 = 144
    dim3 gSq  (DP / 128, DP / 64, BATCH);    // 3 x 6 x 16 = 288
    dim3 gWide(NP / 128, DP / 64, BATCH);    // 17 x 6 x 16 = 1632

    // 1) G = H[:, :2048] @ H[:, :2048]^T   (mask == K-truncation)
    gemm_nt<0, 4><<<gG, blk, smem4>>>(Hb, Hb, S1, nullptr, nullptr,
                                      2048, NP, NP, DP, sHN, sHN, sDD, 1.f);
    // 2) T1 = P @ G  (G symmetric -> B-operand directly)
    gemm_nt<0, 2><<<gSq, blk, smem2>>>(Pb, S1, S2, nullptr, nullptr,
                                       DK, DK, DP, DP, 0, sDD, sDD, 1.f);
    // 3) A2 = T1 @ Q
    gemm_nt<0, 2><<<gSq, blk, smem2>>>(S2, QbT, S1, nullptr, nullptr,
                                       DK, DP, DK, DP, sDD, 0, sDD, 1.f);
    // 4) out = H + (A2 @ H) / 2048
    gemm_nt<1, 2><<<gWide, blk, smem2>>>(S1, HbT, nullptr, out, H,
                                         DK, DP, DP, 0, sDD, sNT, 0, 1.f / 2048.f);
}

// round 16
// speedup vs baseline: 1.1092x; 1.0602x over previous
#include <cuda_runtime.h>
#include <cuda_bf16.h>
#include <cstdint>

// LinearSelfAttention, factored:
//   G  = H[:, :2048] @ H[:, :2048]^T   (mask == K-truncation; G symmetric)
//   T1 = P @ G ;  A2 = T1 @ Q ;  out = H + (A2 @ H) / 2048
// bf16 mma.sync + ldmatrix, SW128 smem, 3-stage cp.async.
// Step 4 is NN (B = Hb via ldmatrix.trans) -> HbT tensor eliminated.

#define BATCH 16
#define D_REAL 257
#define N_REAL 2049
#define HSTR   (257L * 2049L)

#define DP 384      // padded d as M/N (mult of 128)
#define DK 320      // padded d as K   (mult of 64)
#define NP 2176     // padded n        (mult of 128)
#define NSTG 3
#define BK 64       // K per chunk

__device__ __align__(256) __nv_bfloat16 g_Hb [BATCH * DP * NP];
__device__ __align__(256) __nv_bfloat16 g_Pb [DP * DK];
__device__ __align__(256) __nv_bfloat16 g_QbT[DP * DK];
__device__ __align__(256) __nv_bfloat16 g_S1 [BATCH * DP * DP];
__device__ __align__(256) __nv_bfloat16 g_S2 [BATCH * DP * DP];

// ---------------------------------------------------------------- helpers

__device__ __forceinline__ uint32_t smem_u32(const void* p) {
    uint32_t a;
    asm("{ .reg .u64 t; cvta.to.shared.u64 t, %1; cvt.u32.u64 %0, t; }"
        : "=r"(a) : "l"(p));
    return a;
}

__device__ __forceinline__ void cp16s(uint32_t dst, const void* src) {
    asm volatile("cp.async.cg.shared.global [%0], [%1], 16;\n" :: "r"(dst), "l"(src));
}

#define SWZ(off) ((off) ^ (((off) >> 3) & 0x70))

__device__ __forceinline__ void ldm_x4(uint32_t* r, uint32_t addr) {
    asm volatile("ldmatrix.sync.aligned.m8n8.x4.shared.b16 {%0,%1,%2,%3}, [%4];"
                 : "=r"(r[0]), "=r"(r[1]), "=r"(r[2]), "=r"(r[3]) : "r"(addr));
}

__device__ __forceinline__ void ldm_x4_t(uint32_t* r, uint32_t addr) {
    asm volatile("ldmatrix.sync.aligned.m8n8.x4.trans.shared.b16 {%0,%1,%2,%3}, [%4];"
                 : "=r"(r[0]), "=r"(r[1]), "=r"(r[2]), "=r"(r[3]) : "r"(addr));
}

__device__ __forceinline__ void mma16816(float* d, const uint32_t* a,
                                         uint32_t b0, uint32_t b1) {
    asm volatile(
        "mma.sync.aligned.m16n8k16.row.col.f32.bf16.bf16.f32 "
        "{%0,%1,%2,%3}, {%4,%5,%6,%7}, {%8,%9}, {%0,%1,%2,%3};"
        : "+f"(d[0]), "+f"(d[1]), "+f"(d[2]), "+f"(d[3])
        : "r"(a[0]), "r"(a[1]), "r"(a[2]), "r"(a[3]), "r"(b0), "r"(b1));
}

// ---------------------------------------------------------------- converts

__global__ void conv_H(const float* __restrict__ H, __nv_bfloat16* __restrict__ Hb)
{
    __shared__ float t[32][33];
    const int b  = blockIdx.z;
    const int n0 = blockIdx.x * 32;
    const int d0 = blockIdx.y * 32;
    const int tid = threadIdx.x;           // 256
    const int tx = tid & 31, ty = tid >> 5;
    const float* Hp = H + (long)b * HSTR;

    #pragma unroll
    for (int i = 0; i < 4; i++) {
        int d = d0 + ty + i * 8, n = n0 + tx;
        float v = 0.f;
        if (d < D_REAL && n < N_REAL) v = Hp[(long)d * N_REAL + n];
        t[ty + i * 8][tx] = v;
    }
    __syncthreads();

    const int c4 = (tid & 7) * 4;
    const int r  = tid >> 3;
    __nv_bfloat16* Hbp = Hb + (long)b * DP * NP;
    __nv_bfloat162 p0, p1;
    p0.x = __float2bfloat16(t[r][c4 + 0]);
    p0.y = __float2bfloat16(t[r][c4 + 1]);
    p1.x = __float2bfloat16(t[r][c4 + 2]);
    p1.y = __float2bfloat16(t[r][c4 + 3]);
    uint2 u;
    u.x = *(uint32_t*)&p0;
    u.y = *(uint32_t*)&p1;
    *(uint2*)&Hbp[(long)(d0 + r) * NP + n0 + c4] = u;
}

__global__ void conv_P(const float* __restrict__ P, __nv_bfloat16* __restrict__ Pb)
{
    int idx = blockIdx.x * blockDim.x + threadIdx.x;
    if (idx >= DP * DK) return;
    int r = idx / DK, c = idx % DK;
    Pb[idx] = __float2bfloat16((r < D_REAL && c < D_REAL) ? P[r * D_REAL + c] : 0.f);
}

__global__ void conv_QT(const float* __restrict__ Q, __nv_bfloat16* __restrict__ QbT)
{
    int idx = blockIdx.x * blockDim.x + threadIdx.x;
    if (idx >= DP * DK) return;
    int n = idx / DK, k = idx % DK;
    QbT[idx] = __float2bfloat16((n < D_REAL && k < D_REAL) ? Q[k * D_REAL + n] : 0.f);
}

// ---------------------------------------------------------------- GEMM

// TRB=0: C = scale*A@B^T, B[N,K] row-major (NT).
// TRB=1: C = scale*A@B,   B[K,N] row-major (NN, ldmatrix.trans).
// CTA tile (MI*32) x 128, warp tile (MI*16) x 32.
// EPI=0: bf16 to Cb (padded). EPI=1: fp32 out = Hadd + acc*scale via smem
//        restage + full-sector streaming, guarded to 257x2049.
template<int EPI, int MI, int TRB>
__global__ void __launch_bounds__(256, 2)
gemm_nt(const __nv_bfloat16* __restrict__ A,
        const __nv_bfloat16* __restrict__ B,
        __nv_bfloat16* __restrict__ Cb,
        float* __restrict__ Cf,
        const float* __restrict__ Hadd,
        int K, int lda, int ldb, int ldc,
        long sA, long sB, long sC, float scale)
{
    constexpr int BM   = MI * 32;
    constexpr int ASZ  = BM * 128;
    constexpr int SSTR = ASZ + 16384;

    extern __shared__ __align__(1024) char dyn[];
    const int bz = blockIdx.z;
    A += (long)bz * sA;
    B += (long)bz * sB;

    const int bm = blockIdx.y * BM;
    const int bn = blockIdx.x * 128;
    const int tid  = threadIdx.x;
    const int lane = tid & 31;
    const int wid  = tid >> 5;
    const int g    = lane >> 2;
    const int tig  = lane & 3;
    const int wm   = (wid & 1) * (MI * 16);
    const int wn   = (wid >> 1) * 32;

    const uint32_t base = smem_u32(dyn);

    float acc[MI][4][4];
    #pragma unroll
    for (int i = 0; i < MI; i++)
        #pragma unroll
        for (int j = 0; j < 4; j++)
            #pragma unroll
            for (int r = 0; r < 4; r++) acc[i][j][r] = 0.f;

    const uint32_t swx      = (uint32_t)((lane & 7) << 4);
    const uint32_t a_rowoff = (uint32_t)(wm + (lane & 15)) * 128;
    const uint32_t a_koff   = (uint32_t)((lane >> 4) * 16);
    // NT B geometry
    const uint32_t b_rowoff = (uint32_t)(wn + (lane & 7) + ((lane >> 4) & 1) * 8) * 128;
    const uint32_t b_koff   = (uint32_t)(((lane >> 3) & 1) * 16);
    // NN (trans) B geometry: smem tile [64 k-rows][128 n-cols], 256B rows,
    // chunk swizzle c ^= (k & 7).
    const uint32_t bt_row = (uint32_t)(lane & 15) * 256;
    const int      bt_c0  = (wn >> 3) + (lane >> 4);
    const uint32_t bt_sw  = (uint32_t)(lane & 7);

    auto load_chunk = [&](int c) {
        const int st = c % NSTG;
        const uint32_t ab = base + st * SSTR;
        const uint32_t bb = ab + ASZ;
        const int k0 = c * BK;
        #pragma unroll
        for (int i = 0; i < MI; i++) {
            int ch  = tid + i * 256;
            int row = ch >> 3;
            int q   = ch & 7;
            cp16s(ab + SWZ(row * 128 + q * 16),
                  A + (long)(bm + row) * lda + k0 + q * 8);
        }
        if (TRB) {
            #pragma unroll
            for (int i = 0; i < 4; i++) {      // 64 k-rows x 16 chunks
                int ch  = tid + i * 256;
                int row = ch >> 4;             // k row 0..63
                int cc  = ch & 15;             // 16B chunk in n
                cp16s(bb + row * 256 + ((uint32_t)(cc ^ (row & 7)) << 4),
                      B + (long)(k0 + row) * ldb + bn + cc * 8);
            }
        } else {
            #pragma unroll
            for (int i = 0; i < 4; i++) {
                int ch  = tid + i * 256;
                int row = ch >> 3;
                int q   = ch & 7;
                cp16s(bb + SWZ(row * 128 + q * 16),
                      B + (long)(bn + row) * ldb + k0 + q * 8);
            }
        }
        asm volatile("cp.async.commit_group;");
    };

    const int nk = K / BK;
    load_chunk(0);
    load_chunk(1);

    for (int kt = 0; kt < nk; kt++) {
        if (kt + 2 < nk) load_chunk(kt + 2);
        else asm volatile("cp.async.commit_group;");
        asm volatile("cp.async.wait_group %0;" :: "n"(NSTG - 1));
        __syncthreads();

        const uint32_t ab = base + (kt % NSTG) * SSTR;
        const uint32_t bb = ab + ASZ;

        #pragma unroll
        for (int kk = 0; kk < 4; kk++) {
            uint32_t af[MI][4], bf[2][4];
            #pragma unroll
            for (int mi = 0; mi < MI; mi++)
                ldm_x4(af[mi], ab + a_rowoff + mi * 2048
                               + ((uint32_t)(kk * 32) + a_koff ^ swx));
            if (TRB) {
                #pragma unroll
                for (int ng = 0; ng < 2; ng++)
                    ldm_x4_t(bf[ng], bb + (uint32_t)kk * 4096 + bt_row
                                     + ((uint32_t)((bt_c0 + 2 * ng) ^ bt_sw) << 4));
            } else {
                #pragma unroll
                for (int p = 0; p < 2; p++)
                    ldm_x4(bf[p], bb + b_rowoff + p * 2048
                                  + ((uint32_t)(kk * 32) + b_koff ^ swx));
            }
            #pragma unroll
            for (int mi = 0; mi < MI; mi++)
                #pragma unroll
                for (int ni = 0; ni < 4; ni++)
                    mma16816(acc[mi][ni], af[mi],
                             bf[ni >> 1][(ni & 1) * 2], bf[ni >> 1][(ni & 1) * 2 + 1]);
        }
        __syncthreads();
    }

    if (EPI == 0) {
        __nv_bfloat16* Cp = Cb + (long)bz * sC;
        #pragma unroll
        for (int mi = 0; mi < MI; mi++) {
            int r0 = bm + wm + mi * 16 + g;
            #pragma unroll
            for (int ni = 0; ni < 4; ni++) {
                int c = bn + wn + ni * 8 + tig * 2;
                __nv_bfloat162 v01, v23;
                v01.x = __float2bfloat16(acc[mi][ni][0] * scale);
                v01.y = __float2bfloat16(acc[mi][ni][1] * scale);
                v23.x = __float2bfloat16(acc[mi][ni][2] * scale);
                v23.y = __float2bfloat16(acc[mi][ni][3] * scale);
                *(__nv_bfloat162*)&Cp[(long)r0 * ldc + c]       = v01;
                *(__nv_bfloat162*)&Cp[(long)(r0 + 8) * ldc + c] = v23;
            }
        }
    } else {
        float* cs = (float*)dyn;
        #pragma unroll
        for (int mi = 0; mi < MI; mi++)
            #pragma unroll
            for (int ni = 0; ni < 4; ni++)
                #pragma unroll
                for (int half = 0; half < 2; half++) {
                    int row = wm + mi * 16 + g + half * 8;
                    int col = wn + ni * 8 + tig * 2;
                    float2 v;
                    v.x = acc[mi][ni][half * 2 + 0] * scale;
                    v.y = acc[mi][ni][half * 2 + 1] * scale;
                    *(float2*)&cs[row * 128 + col] = v;
                }
        __syncthreads();

        const float* Hp = Hadd + (long)bz * HSTR;
        float*       Op = Cf   + (long)bz * HSTR;
        const int lcol = tid & 127;
        const int gcol = bn + lcol;
        if (gcol < N_REAL) {
            #pragma unroll 4
            for (int rr = tid >> 7; rr < BM; rr += 2) {
                int grow = bm + rr;
                if (grow < D_REAL) {
                    long idx = (long)grow * N_REAL + gcol;
                    float v = Hp[idx] + cs[rr * 128 + lcol];
                    __stcs(&Op[idx], v);
                }
            }
        }
    }
}

// ---------------------------------------------------------------- launch

extern "C" void kernel_launch(void* const* d_in, const int* in_sizes, int n_in,
                              void* d_out, int out_size)
{
    const float* H = (const float*)d_in[0];
    const float* P = (const float*)d_in[1];
    const float* Q = (const float*)d_in[2];
    float* out = (float*)d_out;

    void *pHb, *pPb, *pQbT, *pS1, *pS2;
    cudaGetSymbolAddress(&pHb,  g_Hb);
    cudaGetSymbolAddress(&pPb,  g_Pb);
    cudaGetSymbolAddress(&pQbT, g_QbT);
    cudaGetSymbolAddress(&pS1,  g_S1);
    cudaGetSymbolAddress(&pS2,  g_S2);
    __nv_bfloat16* Hb  = (__nv_bfloat16*)pHb;
    __nv_bfloat16* Pb  = (__nv_bfloat16*)pPb;
    __nv_bfloat16* QbT = (__nv_bfloat16*)pQbT;
    __nv_bfloat16* S1  = (__nv_bfloat16*)pS1;
    __nv_bfloat16* S2  = (__nv_bfloat16*)pS2;

    const long sHN = (long)DP * NP;
    const long sDD = (long)DP * DP;

    conv_H <<<dim3(NP / 32, DP / 32, BATCH), 256>>>(H, Hb);
    conv_P <<<(DP * DK + 255) / 256, 256>>>(P, Pb);
    conv_QT<<<(DP * DK + 255) / 256, 256>>>(Q, QbT);

    const int smem4 = NSTG * (128 * 128 + 16384);   // 96 KB
    const int smem2 = NSTG * (64 * 128 + 16384);    // 72 KB
    cudaFuncSetAttribute(gemm_nt<0, 4, 0>, cudaFuncAttributeMaxDynamicSharedMemorySize, smem4);
    cudaFuncSetAttribute(gemm_nt<0, 2, 0>, cudaFuncAttributeMaxDynamicSharedMemorySize, smem2);
    cudaFuncSetAttribute(gemm_nt<1, 2, 1>, cudaFuncAttributeMaxDynamicSharedMemorySize, smem2);

    dim3 blk(256);
    dim3 gG   (DP / 128, DP / 128, BATCH);   // 144
    dim3 gSq  (DP / 128, DP / 64, BATCH);    // 288
    dim3 gWide(NP / 128, DP / 64, BATCH);    // 1632

    // 1) G = H[:, :2048] @ H[:, :2048]^T
    gemm_nt<0, 4, 0><<<gG, blk, smem4>>>(Hb, Hb, S1, nullptr, nullptr,
                                         2048, NP, NP, DP, sHN, sHN, sDD, 1.f);
    // 2) T1 = P @ G  (G symmetric)
    gemm_nt<0, 2, 0><<<gSq, blk, smem2>>>(Pb, S1, S2, nullptr, nullptr,
                                          DK, DK, DP, DP, 0, sDD, sDD, 1.f);
    // 3) A2 = T1 @ Q
    gemm_nt<0, 2, 0><<<gSq, blk, smem2>>>(S2, QbT, S1, nullptr, nullptr,
                                          DK, DP, DK, DP, sDD, 0, sDD, 1.f);
    // 4) out = H + (A2 @ H) / 2048   (NN: B = Hb)
    gemm_nt<1, 2, 1><<<gWide, blk, smem2>>>(S1, Hb, nullptr, out, H,
                                            DK, DP, NP, 0, sDD, sHN, 0, 1.f / 2048.f);
}